// round 14
// baseline (speedup 1.0000x reference)
#include <cuda_runtime.h>
#include <cuda_bf16.h>
#include <cstdint>

#define BB 2
#define HH 16
#define SS 2048
#define DD 64
#define BH (BB*HH)
#define SCALE 0.125f
#define LOG2E 1.4426950408889634f

static __device__ float g_row_s[BH * SS];
static __device__ __align__(16) uint32_t g_mbits[(size_t)BB * SS * SS / 32];  // 1MB
// bf16 hi/lo scratch (packed bf16x2), PAIR-PERMUTED [0,4,1,5,2,6,3,7] within
// each 32B group. K: [bh][key][d], V: [bh][d][key]
static __device__ __align__(16) uint32_t g_kh[(size_t)BH * SS * DD / 2];
static __device__ __align__(16) uint32_t g_kl[(size_t)BH * SS * DD / 2];
static __device__ __align__(16) uint32_t g_vth[(size_t)BH * SS * DD / 2];
static __device__ __align__(16) uint32_t g_vtl[(size_t)BH * SS * DD / 2];

// ---------------------------------------------------------------------------
// helpers
// ---------------------------------------------------------------------------
__device__ __forceinline__ float ex2(float x) {
    float r;
    asm("ex2.approx.f32 %0, %1;" : "=f"(r) : "f"(x));
    return r;
}
__device__ __forceinline__ void pack_hl(float a, float b, uint32_t& h, uint32_t& l) {
    asm("cvt.rn.bf16x2.f32 %0, %1, %2;" : "=r"(h) : "f"(b), "f"(a));
    float ha = __uint_as_float(h << 16);
    float hb = __uint_as_float(h & 0xffff0000u);
    asm("cvt.rn.bf16x2.f32 %0, %1, %2;" : "=r"(l) : "f"(b - hb), "f"(a - ha));
}
__device__ __forceinline__ uint32_t smem_u32(const void* p) {
    uint32_t a;
    asm("{ .reg .u64 t; cvta.to.shared.u64 t, %1; cvt.u32.u64 %0, t; }"
        : "=r"(a) : "l"(p));
    return a;
}
#define CPA16(dst, src) \
    asm volatile("cp.async.cg.shared.global [%0], [%1], 16;" :: "r"(dst), "l"(src))
#define CPA_COMMIT() asm volatile("cp.async.commit_group;" ::: "memory")
#define CPA_WAIT0()  asm volatile("cp.async.wait_group 0;" ::: "memory")

// mma.sync m16n8k16 row.col f32.bf16.bf16.f32 — D accumulates in place
#define MMA(d, a, b0v, b1v) \
    asm volatile("mma.sync.aligned.m16n8k16.row.col.f32.bf16.bf16.f32 " \
        "{%0,%1,%2,%3}, {%4,%5,%6,%7}, {%8,%9}, {%0,%1,%2,%3};" \
        : "+f"((d)[0]), "+f"((d)[1]), "+f"((d)[2]), "+f"((d)[3]) \
        : "r"((a)[0]), "r"((a)[1]), "r"((a)[2]), "r"((a)[3]), "r"(b0v), "r"(b1v))

// Pass A smem: single-buffer K tile [key 128][d 64] bf16, row stride 160B (hi+lo)
#define A_KH 0
#define A_KL 20480
#define SMEM_A 40960
// Pass B smem: single-buffer V tile [d 64][key 128] bf16, row stride 288B (hi+lo)
#define B_VH 0
#define B_VL 18432
#define SMEM_B 36864

// ---------------------------------------------------------------------------
// Kernel 0: bit-pack the int32 mask
// ---------------------------------------------------------------------------
__global__ __launch_bounds__(256)
void mask_pack(const int* __restrict__ mask)
{
    const size_t w = (size_t)blockIdx.x * 256 + threadIdx.x;
    const int4* p = (const int4*)mask + w * 8;
    uint32_t bits = 0;
    #pragma unroll
    for (int j = 0; j < 8; j++) {
        int4 x = p[j];
        bits |= (x.x ? 1u : 0u) << (j * 4 + 0);
        bits |= (x.y ? 1u : 0u) << (j * 4 + 1);
        bits |= (x.z ? 1u : 0u) << (j * 4 + 2);
        bits |= (x.w ? 1u : 0u) << (j * 4 + 3);
    }
    g_mbits[w] = bits;
}

// ---------------------------------------------------------------------------
// Kernel 0b: K -> bf16 hi/lo, pair-permuted within each 32B (8-pair) group.
// ---------------------------------------------------------------------------
__global__ __launch_bounds__(256)
void conv_k(const float* __restrict__ k)
{
    const size_t gi = (size_t)blockIdx.x * 256 + threadIdx.x;
    const float* kp = k + gi * 16;
    uint32_t h[8], l[8];
    #pragma unroll
    for (int i = 0; i < 4; i++) {
        float4 f = *(const float4*)(kp + i * 4);
        pack_hl(f.x, f.y, h[i*2+0], l[i*2+0]);
        pack_hl(f.z, f.w, h[i*2+1], l[i*2+1]);
    }
    *(uint4*)(g_kh + gi * 8)     = make_uint4(h[0], h[4], h[1], h[5]);
    *(uint4*)(g_kh + gi * 8 + 4) = make_uint4(h[2], h[6], h[3], h[7]);
    *(uint4*)(g_kl + gi * 8)     = make_uint4(l[0], l[4], l[1], l[5]);
    *(uint4*)(g_kl + gi * 8 + 4) = make_uint4(l[2], l[6], l[3], l[7]);
}

// ---------------------------------------------------------------------------
// Kernel 0c: V -> bf16 hi/lo transposed [bh][d][key], pair-permuted per group.
// ---------------------------------------------------------------------------
__global__ __launch_bounds__(256)
void conv_vt(const float* __restrict__ v)
{
    __shared__ float ts[64][65];
    const int tid = threadIdx.x;
    const int bh  = blockIdx.y;
    const int n0  = blockIdx.x * 64;

    const int r  = tid >> 2;
    const int c0 = (tid & 3) * 16;
    const float* vp = v + ((size_t)bh * SS + n0 + r) * DD + c0;
    #pragma unroll
    for (int i = 0; i < 4; i++) {
        float4 f = *(const float4*)(vp + i * 4);
        ts[r][c0 + i*4 + 0] = f.x;
        ts[r][c0 + i*4 + 1] = f.y;
        ts[r][c0 + i*4 + 2] = f.z;
        ts[r][c0 + i*4 + 3] = f.w;
    }
    __syncthreads();

    const int d  = tid >> 2;
    const int kc = (tid & 3) * 16;
    uint32_t h[8], l[8];
    #pragma unroll
    for (int m = 0; m < 8; m++)
        pack_hl(ts[kc + 2*m][d], ts[kc + 2*m + 1][d], h[m], l[m]);
    const size_t o = (((size_t)bh * DD + d) * SS + n0 + kc) / 2;
    *(uint4*)(g_vth + o)     = make_uint4(h[0], h[4], h[1], h[5]);
    *(uint4*)(g_vth + o + 4) = make_uint4(h[2], h[6], h[3], h[7]);
    *(uint4*)(g_vtl + o)     = make_uint4(l[0], l[4], l[1], l[5]);
    *(uint4*)(g_vtl + o + 4) = make_uint4(l[2], l[6], l[3], l[7]);
}

// ---------------------------------------------------------------------------
// Q fragments (hi/lo), scale*log2e folded in
// ---------------------------------------------------------------------------
__device__ __forceinline__ void load_q_frags(const float* __restrict__ q,
                                             int bh, int r0, int r8, int t,
                                             uint32_t (&qh)[4][4], uint32_t (&ql)[4][4])
{
    const float* qp = q + (size_t)bh * SS * DD;
    const float sc = SCALE * LOG2E;
    #pragma unroll
    for (int ks = 0; ks < 4; ks++) {
        const int c = ks * 16 + t * 2;
        float2 x0 = *(const float2*)(qp + (size_t)r0 * DD + c);
        float2 x1 = *(const float2*)(qp + (size_t)r8 * DD + c);
        float2 x2 = *(const float2*)(qp + (size_t)r0 * DD + c + 8);
        float2 x3 = *(const float2*)(qp + (size_t)r8 * DD + c + 8);
        pack_hl(x0.x * sc, x0.y * sc, qh[ks][0], ql[ks][0]);
        pack_hl(x1.x * sc, x1.y * sc, qh[ks][1], ql[ks][1]);
        pack_hl(x2.x * sc, x2.y * sc, qh[ks][2], ql[ks][2]);
        pack_hl(x3.x * sc, x3.y * sc, qh[ks][3], ql[ks][3]);
    }
}

// ---------------------------------------------------------------------------
// Pass A: QK (bf16x3) -> e = exp(masked score) -> atten (unnormalized), rowsums.
// Single-buffered K tiles, 3 CTAs/SM.
// ---------------------------------------------------------------------------
__global__ void __launch_bounds__(256, 3)
sdpa_qk(const float* __restrict__ q, float* __restrict__ atten)
{
    extern __shared__ char smem[];
    const int tid  = threadIdx.x;
    const int lane = tid & 31;
    const int g    = lane >> 2;
    const int t    = lane & 3;
    const int w    = tid >> 5;
    const int bh   = blockIdx.y;
    const int b    = bh / HH;
    const int q0   = blockIdx.x * 128;
    const int r0   = q0 + w * 16 + g;
    const int r8   = r0 + 8;
    const uint32_t sb = smem_u32(smem);

    const size_t mb0 = ((size_t)b * SS + r0) * 64;
    const size_t mb8 = ((size_t)b * SS + r8) * 64;
    float* arow_g  = atten + ((size_t)bh * SS + r0) * SS;
    float* arow_g8 = atten + ((size_t)bh * SS + r8) * SS;

    const char* kh_b = (const char*)g_kh + (size_t)bh * SS * DD * 2;
    const char* kl_b = (const char*)g_kl + (size_t)bh * SS * DD * 2;

    uint32_t qh[4][4], ql[4][4];
    load_q_frags(q, bh, r0, r8, t, qh, ql);

    float sum_g = 0.0f, sum_g8 = 0.0f;

    #pragma unroll 1
    for (int kt = 0; kt < 16; kt++) {
        const int n0 = kt * 128;
        __syncthreads();   // previous compute done with smem
        #pragma unroll
        for (int cc = 0; cc < 4; cc++) {
            const int c  = tid + cc * 256;
            const int kr = c >> 3, kc = c & 7;
            const size_t src = (size_t)(n0 + kr) * (DD * 2) + kc * 16;
            const uint32_t dst = kr * 160 + kc * 16;
            CPA16(sb + A_KH + dst, kh_b + src);
            CPA16(sb + A_KL + dst, kl_b + src);
        }
        CPA_COMMIT();
        CPA_WAIT0();
        __syncthreads();

        uint4 mg = *(const uint4*)(g_mbits + mb0 + n0 / 32);
        uint4 m8 = *(const uint4*)(g_mbits + mb8 + n0 / 32);
        const uint32_t* mgw = (const uint32_t*)&mg;
        const uint32_t* m8w = (const uint32_t*)&m8;

        #pragma unroll
        for (int h = 0; h < 2; h++) {
            float s[8][4];
            #pragma unroll
            for (int nt = 0; nt < 8; nt++)
                #pragma unroll
                for (int i = 0; i < 4; i++) s[nt][i] = 0.0f;

            #pragma unroll
            for (int ks = 0; ks < 4; ks++) {
                #pragma unroll
                for (int pass = 0; pass < 3; pass++) {
                    const uint32_t* A = (pass == 2) ? ql[ks] : qh[ks];
                    const int bb = (pass == 1) ? A_KL : A_KH;
                    #pragma unroll
                    for (int nt = 0; nt < 8; nt++) {
                        const char* ad = smem + bb + ((h * 8 + nt) * 8 + g) * 160
                                       + ks * 32 + t * 8;
                        uint2 b01 = *(const uint2*)ad;   // LDS.64 pairs (p, p+4)
                        MMA(s[nt], A, b01.x, b01.y);
                    }
                }
            }

            #pragma unroll
            for (int nt = 0; nt < 8; nt++) {
                const int ntg = h * 8 + nt;
                const uint32_t wg = mgw[ntg >> 2] >> ((ntg & 3) * 8 + t * 2);
                const uint32_t w8 = m8w[ntg >> 2] >> ((ntg & 3) * 8 + t * 2);
                const float e0 = (wg      & 1) ? 0.0f : ex2(s[nt][0]);
                const float e1 = (wg >> 1 & 1) ? 0.0f : ex2(s[nt][1]);
                const float e2 = (w8      & 1) ? 0.0f : ex2(s[nt][2]);
                const float e3 = (w8 >> 1 & 1) ? 0.0f : ex2(s[nt][3]);
                sum_g  += e0 + e1;
                sum_g8 += e2 + e3;
                const int c = n0 + ntg * 8 + t * 2;
                __stcs((float2*)(arow_g  + c), make_float2(e0, e1));
                __stcs((float2*)(arow_g8 + c), make_float2(e2, e3));
            }
        }
    }

    sum_g  += __shfl_xor_sync(0xffffffffu, sum_g, 1);
    sum_g  += __shfl_xor_sync(0xffffffffu, sum_g, 2);
    sum_g8 += __shfl_xor_sync(0xffffffffu, sum_g8, 1);
    sum_g8 += __shfl_xor_sync(0xffffffffu, sum_g8, 2);
    if (t == 0) {
        g_row_s[bh * SS + r0] = sum_g;
        g_row_s[bh * SS + r8] = sum_g8;
    }
}

// ---------------------------------------------------------------------------
// Pass B: p = e/sum -> atten (final), out = P V. Single-buffered V tiles, 3 CTAs/SM.
// ---------------------------------------------------------------------------
__global__ void __launch_bounds__(256, 3)
sdpa_av(float* __restrict__ atten, float* __restrict__ out)
{
    extern __shared__ char smem[];
    const int tid  = threadIdx.x;
    const int lane = tid & 31;
    const int g    = lane >> 2;
    const int t    = lane & 3;
    const int w    = tid >> 5;
    const int bh   = blockIdx.y;
    const int q0   = blockIdx.x * 128;
    const int r0   = q0 + w * 16 + g;
    const int r8   = r0 + 8;
    const uint32_t sb = smem_u32(smem);

    float* arow_g  = atten + ((size_t)bh * SS + r0) * SS;
    float* arow_g8 = atten + ((size_t)bh * SS + r8) * SS;

    const char* vh_b = (const char*)g_vth + (size_t)bh * SS * DD * 2;
    const char* vl_b = (const char*)g_vtl + (size_t)bh * SS * DD * 2;

    const float inv_g  = 1.0f / g_row_s[bh * SS + r0];
    const float inv_g8 = 1.0f / g_row_s[bh * SS + r8];

    float o[8][4];
    #pragma unroll
    for (int nd = 0; nd < 8; nd++)
        #pragma unroll
        for (int i = 0; i < 4; i++) o[nd][i] = 0.0f;

    #pragma unroll 1
    for (int kt = 0; kt < 16; kt++) {
        const int n0 = kt * 128;
        __syncthreads();   // previous compute done with smem
        #pragma unroll
        for (int cc = 0; cc < 4; cc++) {
            const int c  = tid + cc * 256;
            const int vd = c >> 4, vc = c & 15;
            const size_t src = ((size_t)vd * SS + n0) * 2 + vc * 16;
            const uint32_t dst = vd * 288 + vc * 16;
            CPA16(sb + B_VH + dst, vh_b + src);
            CPA16(sb + B_VL + dst, vl_b + src);
        }
        CPA_COMMIT();
        CPA_WAIT0();
        __syncthreads();

        #pragma unroll
        for (int h = 0; h < 2; h++) {
            // load this half's e values (independent streaming loads)
            float2 eg[8], e8[8];
            #pragma unroll
            for (int nt = 0; nt < 8; nt++) {
                const int c = n0 + (h * 8 + nt) * 8 + t * 2;
                eg[nt] = __ldcs((const float2*)(arow_g  + c));
                e8[nt] = __ldcs((const float2*)(arow_g8 + c));
            }

            #pragma unroll
            for (int kap = 0; kap < 4; kap++) {
                uint32_t ah[4], al[4];
                #pragma unroll
                for (int i = 0; i < 2; i++) {
                    const int nt = kap * 2 + i;
                    const float p0 = eg[nt].x * inv_g;
                    const float p1 = eg[nt].y * inv_g;
                    const float p2 = e8[nt].x * inv_g8;
                    const float p3 = e8[nt].y * inv_g8;
                    const int c = n0 + (h * 8 + nt) * 8 + t * 2;
                    __stcs((float2*)(arow_g  + c), make_float2(p0, p1));
                    __stcs((float2*)(arow_g8 + c), make_float2(p2, p3));
                    pack_hl(p0, p1, ah[i*2+0], al[i*2+0]);
                    pack_hl(p2, p3, ah[i*2+1], al[i*2+1]);
                }
                #pragma unroll
                for (int nd = 0; nd < 8; nd++) {
                    const int vbase = (nd * 8 + g) * 288 + (h * 4 + kap) * 32 + t * 8;
                    uint2 vh2 = *(const uint2*)(smem + B_VH + vbase);
                    uint2 vl2 = *(const uint2*)(smem + B_VL + vbase);
                    MMA(o[nd], ah, vh2.x, vh2.y);
                    MMA(o[nd], ah, vl2.x, vl2.y);
                    MMA(o[nd], al, vh2.x, vh2.y);
                }
            }
        }
    }

    float* orow_g  = out + ((size_t)bh * SS + r0) * DD;
    float* orow_g8 = out + ((size_t)bh * SS + r8) * DD;
    #pragma unroll
    for (int nd = 0; nd < 8; nd++) {
        *(float2*)(orow_g  + nd * 8 + t * 2) = make_float2(o[nd][0], o[nd][1]);
        *(float2*)(orow_g8 + nd * 8 + t * 2) = make_float2(o[nd][2], o[nd][3]);
    }
}

// ---------------------------------------------------------------------------
extern "C" void kernel_launch(void* const* d_in, const int* in_sizes, int n_in,
                              void* d_out, int out_size)
{
    const float* q = (const float*)d_in[0];
    const float* k = (const float*)d_in[1];
    const float* v = (const float*)d_in[2];
    const int*   mask = (const int*)d_in[3];

    float* out   = (float*)d_out;                 // [B,H,S,D]
    float* atten = out + (size_t)BH * SS * DD;    // [B,H,S,S]

    cudaFuncSetAttribute(sdpa_qk, cudaFuncAttributeMaxDynamicSharedMemorySize, SMEM_A);
    cudaFuncSetAttribute(sdpa_av, cudaFuncAttributeMaxDynamicSharedMemorySize, SMEM_B);

    mask_pack<<<1024, 256>>>(mask);
    conv_k<<<BH * SS * DD / (256 * 16), 256>>>(k);
    conv_vt<<<dim3(SS / 64, BH), 256>>>(v);
    dim3 grid(SS / 128, BH);
    sdpa_qk<<<grid, 256, SMEM_A>>>(q, atten);
    sdpa_av<<<grid, 256, SMEM_B>>>(atten, out);
    (void)in_sizes; (void)n_in; (void)out_size;
}

// round 15
// speedup vs baseline: 1.2105x; 1.2105x over previous
#include <cuda_runtime.h>
#include <cuda_bf16.h>
#include <cstdint>

#define BB 2
#define HH 16
#define SS 2048
#define DD 64
#define BH (BB*HH)
#define SCALE 0.125f
#define LOG2E 1.4426950408889634f

static __device__ float g_row_s[BH * SS];
static __device__ __align__(16) uint32_t g_mbits[(size_t)BB * SS * SS / 32];  // 1MB
// bf16 hi/lo scratch (packed bf16x2), PAIR-PERMUTED [0,4,1,5,2,6,3,7] within
// each 32B group. K: [bh][key][d], V: [bh][d][key]
static __device__ __align__(16) uint32_t g_kh[(size_t)BH * SS * DD / 2];
static __device__ __align__(16) uint32_t g_kl[(size_t)BH * SS * DD / 2];
static __device__ __align__(16) uint32_t g_vth[(size_t)BH * SS * DD / 2];
static __device__ __align__(16) uint32_t g_vtl[(size_t)BH * SS * DD / 2];
// e = exp(score) as packed bf16 hi/lo fragment words: [bh][row][col/2] -> (h, l)
static __device__ __align__(16) uint2 g_ehl[(size_t)BH * SS * SS / 2];

// ---------------------------------------------------------------------------
// helpers
// ---------------------------------------------------------------------------
__device__ __forceinline__ float ex2(float x) {
    float r;
    asm("ex2.approx.f32 %0, %1;" : "=f"(r) : "f"(x));
    return r;
}
__device__ __forceinline__ void pack_hl(float a, float b, uint32_t& h, uint32_t& l) {
    asm("cvt.rn.bf16x2.f32 %0, %1, %2;" : "=r"(h) : "f"(b), "f"(a));
    float ha = __uint_as_float(h << 16);
    float hb = __uint_as_float(h & 0xffff0000u);
    asm("cvt.rn.bf16x2.f32 %0, %1, %2;" : "=r"(l) : "f"(b - hb), "f"(a - ha));
}
__device__ __forceinline__ float2 bf2f(uint32_t w) {
    __nv_bfloat162 b;
    *(uint32_t*)&b = w;
    return __bfloat1622float2(b);
}
__device__ __forceinline__ uint32_t smem_u32(const void* p) {
    uint32_t a;
    asm("{ .reg .u64 t; cvta.to.shared.u64 t, %1; cvt.u32.u64 %0, t; }"
        : "=r"(a) : "l"(p));
    return a;
}
#define CPA16(dst, src) \
    asm volatile("cp.async.cg.shared.global [%0], [%1], 16;" :: "r"(dst), "l"(src))
#define CPA_COMMIT() asm volatile("cp.async.commit_group;" ::: "memory")
#define CPA_WAIT(n)  asm volatile("cp.async.wait_group %0;" :: "n"(n) : "memory")

// mma.sync m16n8k16 row.col f32.bf16.bf16.f32 — D accumulates in place
#define MMA(d, a, b0v, b1v) \
    asm volatile("mma.sync.aligned.m16n8k16.row.col.f32.bf16.bf16.f32 " \
        "{%0,%1,%2,%3}, {%4,%5,%6,%7}, {%8,%9}, {%0,%1,%2,%3};" \
        : "+f"((d)[0]), "+f"((d)[1]), "+f"((d)[2]), "+f"((d)[3]) \
        : "r"((a)[0]), "r"((a)[1]), "r"((a)[2]), "r"((a)[3]), "r"(b0v), "r"(b1v))

// Pass A smem: double-buffered K tiles [key 128][d 64] bf16, row stride 160B.
#define A_KH 0
#define A_KL 20480
#define A_BUF 40960
#define SMEM_A (2 * A_BUF)          // 81920

// Pass B smem: double-buffered V tiles [d 64][key 128] bf16, row stride 288B.
#define B_VH 0
#define B_VL 18432
#define B_BUF 36864
#define SMEM_B (2 * B_BUF)          // 73728

// ---------------------------------------------------------------------------
// Kernel 0: bit-pack the int32 mask
// ---------------------------------------------------------------------------
__global__ __launch_bounds__(256)
void mask_pack(const int* __restrict__ mask)
{
    const size_t w = (size_t)blockIdx.x * 256 + threadIdx.x;
    const int4* p = (const int4*)mask + w * 8;
    uint32_t bits = 0;
    #pragma unroll
    for (int j = 0; j < 8; j++) {
        int4 x = p[j];
        bits |= (x.x ? 1u : 0u) << (j * 4 + 0);
        bits |= (x.y ? 1u : 0u) << (j * 4 + 1);
        bits |= (x.z ? 1u : 0u) << (j * 4 + 2);
        bits |= (x.w ? 1u : 0u) << (j * 4 + 3);
    }
    g_mbits[w] = bits;
}

// ---------------------------------------------------------------------------
// Kernel 0b: K -> bf16 hi/lo, pair-permuted within each 32B (8-pair) group.
// ---------------------------------------------------------------------------
__global__ __launch_bounds__(256)
void conv_k(const float* __restrict__ k)
{
    const size_t gi = (size_t)blockIdx.x * 256 + threadIdx.x;
    const float* kp = k + gi * 16;
    uint32_t h[8], l[8];
    #pragma unroll
    for (int i = 0; i < 4; i++) {
        float4 f = *(const float4*)(kp + i * 4);
        pack_hl(f.x, f.y, h[i*2+0], l[i*2+0]);
        pack_hl(f.z, f.w, h[i*2+1], l[i*2+1]);
    }
    *(uint4*)(g_kh + gi * 8)     = make_uint4(h[0], h[4], h[1], h[5]);
    *(uint4*)(g_kh + gi * 8 + 4) = make_uint4(h[2], h[6], h[3], h[7]);
    *(uint4*)(g_kl + gi * 8)     = make_uint4(l[0], l[4], l[1], l[5]);
    *(uint4*)(g_kl + gi * 8 + 4) = make_uint4(l[2], l[6], l[3], l[7]);
}

// ---------------------------------------------------------------------------
// Kernel 0c: V -> bf16 hi/lo transposed [bh][d][key], pair-permuted per group.
// ---------------------------------------------------------------------------
__global__ __launch_bounds__(256)
void conv_vt(const float* __restrict__ v)
{
    __shared__ float ts[64][65];
    const int tid = threadIdx.x;
    const int bh  = blockIdx.y;
    const int n0  = blockIdx.x * 64;

    const int r  = tid >> 2;
    const int c0 = (tid & 3) * 16;
    const float* vp = v + ((size_t)bh * SS + n0 + r) * DD + c0;
    #pragma unroll
    for (int i = 0; i < 4; i++) {
        float4 f = *(const float4*)(vp + i * 4);
        ts[r][c0 + i*4 + 0] = f.x;
        ts[r][c0 + i*4 + 1] = f.y;
        ts[r][c0 + i*4 + 2] = f.z;
        ts[r][c0 + i*4 + 3] = f.w;
    }
    __syncthreads();

    const int d  = tid >> 2;
    const int kc = (tid & 3) * 16;
    uint32_t h[8], l[8];
    #pragma unroll
    for (int m = 0; m < 8; m++)
        pack_hl(ts[kc + 2*m][d], ts[kc + 2*m + 1][d], h[m], l[m]);
    const size_t o = (((size_t)bh * DD + d) * SS + n0 + kc) / 2;
    *(uint4*)(g_vth + o)     = make_uint4(h[0], h[4], h[1], h[5]);
    *(uint4*)(g_vth + o + 4) = make_uint4(h[2], h[6], h[3], h[7]);
    *(uint4*)(g_vtl + o)     = make_uint4(l[0], l[4], l[1], l[5]);
    *(uint4*)(g_vtl + o + 4) = make_uint4(l[2], l[6], l[3], l[7]);
}

// ---------------------------------------------------------------------------
// Q fragments (hi/lo), scale*log2e folded in
// ---------------------------------------------------------------------------
__device__ __forceinline__ void load_q_frags(const float* __restrict__ q,
                                             int bh, int r0, int r8, int t,
                                             uint32_t (&qh)[4][4], uint32_t (&ql)[4][4])
{
    const float* qp = q + (size_t)bh * SS * DD;
    const float sc = SCALE * LOG2E;
    #pragma unroll
    for (int ks = 0; ks < 4; ks++) {
        const int c = ks * 16 + t * 2;
        float2 x0 = *(const float2*)(qp + (size_t)r0 * DD + c);
        float2 x1 = *(const float2*)(qp + (size_t)r8 * DD + c);
        float2 x2 = *(const float2*)(qp + (size_t)r0 * DD + c + 8);
        float2 x3 = *(const float2*)(qp + (size_t)r8 * DD + c + 8);
        pack_hl(x0.x * sc, x0.y * sc, qh[ks][0], ql[ks][0]);
        pack_hl(x1.x * sc, x1.y * sc, qh[ks][1], ql[ks][1]);
        pack_hl(x2.x * sc, x2.y * sc, qh[ks][2], ql[ks][2]);
        pack_hl(x3.x * sc, x3.y * sc, qh[ks][3], ql[ks][3]);
    }
}

// ---------------------------------------------------------------------------
// Pass A: QK (bf16x3) -> e = exp(masked score) -> g_ehl (bf16 hi/lo words),
// rowsums. K tiles double-buffered via cp.async. (R13 structure.)
// ---------------------------------------------------------------------------
__device__ __forceinline__ void stage_k(uint32_t sbuf, const char* kh_b,
                                        const char* kl_b, int n0, int tid)
{
    #pragma unroll
    for (int cc = 0; cc < 4; cc++) {
        const int c  = tid + cc * 256;          // 0..1023
        const int kr = c >> 3, kc = c & 7;
        const size_t src = (size_t)(n0 + kr) * (DD * 2) + kc * 16;
        const uint32_t dst = kr * 160 + kc * 16;
        CPA16(sbuf + A_KH + dst, kh_b + src);
        CPA16(sbuf + A_KL + dst, kl_b + src);
    }
}

__global__ void __launch_bounds__(256, 2)
sdpa_qk(const float* __restrict__ q)
{
    extern __shared__ char smem[];
    const int tid  = threadIdx.x;
    const int lane = tid & 31;
    const int g    = lane >> 2;
    const int t    = lane & 3;
    const int w    = tid >> 5;
    const int bh   = blockIdx.y;
    const int b    = bh / HH;
    const int q0   = blockIdx.x * 128;
    const int r0   = q0 + w * 16 + g;
    const int r8   = r0 + 8;
    const uint32_t sb = smem_u32(smem);

    const size_t mb0 = ((size_t)b * SS + r0) * 64;
    const size_t mb8 = ((size_t)b * SS + r8) * 64;
    uint2* ehl_g  = g_ehl + ((size_t)bh * SS + r0) * (SS / 2);
    uint2* ehl_g8 = g_ehl + ((size_t)bh * SS + r8) * (SS / 2);

    const char* kh_b = (const char*)g_kh + (size_t)bh * SS * DD * 2;
    const char* kl_b = (const char*)g_kl + (size_t)bh * SS * DD * 2;

    // prologue: stage tile 0; overlap q-fragment conversion with it
    stage_k(sb, kh_b, kl_b, 0, tid);
    CPA_COMMIT();

    uint32_t qh[4][4], ql[4][4];
    load_q_frags(q, bh, r0, r8, t, qh, ql);

    float sum_g = 0.0f, sum_g8 = 0.0f;

    #pragma unroll 1
    for (int kt = 0; kt < 16; kt++) {
        const int n0 = kt * 128;
        const char* bufc = smem + (kt & 1) * A_BUF;

        if (kt + 1 < 16) {
            stage_k(sb + ((kt + 1) & 1) * A_BUF, kh_b, kl_b, (kt + 1) * 128, tid);
            CPA_COMMIT();
            CPA_WAIT(1);
        } else {
            CPA_WAIT(0);
        }
        __syncthreads();

        uint4 mg = *(const uint4*)(g_mbits + mb0 + n0 / 32);
        uint4 m8 = *(const uint4*)(g_mbits + mb8 + n0 / 32);
        const uint32_t* mgw = (const uint32_t*)&mg;
        const uint32_t* m8w = (const uint32_t*)&m8;

        #pragma unroll
        for (int h = 0; h < 2; h++) {
            float s[8][4];
            #pragma unroll
            for (int nt = 0; nt < 8; nt++)
                #pragma unroll
                for (int i = 0; i < 4; i++) s[nt][i] = 0.0f;

            #pragma unroll
            for (int ks = 0; ks < 4; ks++) {
                #pragma unroll
                for (int pass = 0; pass < 3; pass++) {
                    const uint32_t* A = (pass == 2) ? ql[ks] : qh[ks];
                    const int bb = (pass == 1) ? A_KL : A_KH;
                    #pragma unroll
                    for (int nt = 0; nt < 8; nt++) {
                        const char* ad = bufc + bb + ((h * 8 + nt) * 8 + g) * 160
                                       + ks * 32 + t * 8;
                        uint2 b01 = *(const uint2*)ad;   // LDS.64 pairs (p, p+4)
                        MMA(s[nt], A, b01.x, b01.y);
                    }
                }
            }

            #pragma unroll
            for (int nt = 0; nt < 8; nt++) {
                const int ntg = h * 8 + nt;
                const uint32_t wg = mgw[ntg >> 2] >> ((ntg & 3) * 8 + t * 2);
                const uint32_t w8 = m8w[ntg >> 2] >> ((ntg & 3) * 8 + t * 2);
                const float e0 = (wg      & 1) ? 0.0f : ex2(s[nt][0]);
                const float e1 = (wg >> 1 & 1) ? 0.0f : ex2(s[nt][1]);
                const float e2 = (w8      & 1) ? 0.0f : ex2(s[nt][2]);
                const float e3 = (w8 >> 1 & 1) ? 0.0f : ex2(s[nt][3]);
                sum_g  += e0 + e1;
                sum_g8 += e2 + e3;
                uint32_t h01, l01, h23, l23;
                pack_hl(e0, e1, h01, l01);
                pack_hl(e2, e3, h23, l23);
                const int cw = (n0 + ntg * 8) / 2 + t;   // word index in row
                __stcs(ehl_g  + cw, make_uint2(h01, l01));
                __stcs(ehl_g8 + cw, make_uint2(h23, l23));
            }
        }
        __syncthreads();   // buf[kt&1] fully read before iter kt+1 restages it
    }

    sum_g  += __shfl_xor_sync(0xffffffffu, sum_g, 1);
    sum_g  += __shfl_xor_sync(0xffffffffu, sum_g, 2);
    sum_g8 += __shfl_xor_sync(0xffffffffu, sum_g8, 1);
    sum_g8 += __shfl_xor_sync(0xffffffffu, sum_g8, 2);
    if (t == 0) {
        g_row_s[bh * SS + r0] = sum_g;
        g_row_s[bh * SS + r8] = sum_g8;
    }
}

// ---------------------------------------------------------------------------
// Pass B: A-frags directly from g_ehl; atten = (h+l)*inv; out = (sum e*V)*inv.
// V tiles double-buffered. (R13 structure.)
// ---------------------------------------------------------------------------
__device__ __forceinline__ void stage_v(uint32_t sbuf, const char* vh_b,
                                        const char* vl_b, int n0, int tid)
{
    #pragma unroll
    for (int cc = 0; cc < 4; cc++) {
        const int c  = tid + cc * 256;          // 0..1023
        const int vd = c >> 4, vc = c & 15;
        const size_t src = ((size_t)vd * SS + n0) * 2 + vc * 16;
        const uint32_t dst = vd * 288 + vc * 16;
        CPA16(sbuf + B_VH + dst, vh_b + src);
        CPA16(sbuf + B_VL + dst, vl_b + src);
    }
}

__global__ void __launch_bounds__(256, 2)
sdpa_av(float* __restrict__ atten, float* __restrict__ out)
{
    extern __shared__ char smem[];
    const int tid  = threadIdx.x;
    const int lane = tid & 31;
    const int g    = lane >> 2;
    const int t    = lane & 3;
    const int w    = tid >> 5;
    const int bh   = blockIdx.y;
    const int q0   = blockIdx.x * 128;
    const int r0   = q0 + w * 16 + g;
    const int r8   = r0 + 8;
    const uint32_t sb = smem_u32(smem);

    float* arow_g  = atten + ((size_t)bh * SS + r0) * SS;
    float* arow_g8 = atten + ((size_t)bh * SS + r8) * SS;
    const uint2* ehl_g  = g_ehl + ((size_t)bh * SS + r0) * (SS / 2);
    const uint2* ehl_g8 = g_ehl + ((size_t)bh * SS + r8) * (SS / 2);

    const char* vh_b = (const char*)g_vth + (size_t)bh * SS * DD * 2;
    const char* vl_b = (const char*)g_vtl + (size_t)bh * SS * DD * 2;

    stage_v(sb, vh_b, vl_b, 0, tid);
    CPA_COMMIT();

    const float inv_g  = 1.0f / g_row_s[bh * SS + r0];
    const float inv_g8 = 1.0f / g_row_s[bh * SS + r8];

    float o[8][4];
    #pragma unroll
    for (int nd = 0; nd < 8; nd++)
        #pragma unroll
        for (int i = 0; i < 4; i++) o[nd][i] = 0.0f;

    #pragma unroll 1
    for (int kt = 0; kt < 16; kt++) {
        const int n0 = kt * 128;
        const char* bufc = smem + (kt & 1) * B_BUF;

        if (kt + 1 < 16) {
            stage_v(sb + ((kt + 1) & 1) * B_BUF, vh_b, vl_b, (kt + 1) * 128, tid);
            CPA_COMMIT();
            CPA_WAIT(1);
        } else {
            CPA_WAIT(0);
        }
        __syncthreads();

        #pragma unroll
        for (int h = 0; h < 2; h++) {
            // load this half's fragment words (independent streaming loads)
            uint2 eg[8], e8[8];
            #pragma unroll
            for (int nt = 0; nt < 8; nt++) {
                const int cw = (n0 + (h * 8 + nt) * 8) / 2 + t;
                eg[nt] = __ldcs(ehl_g  + cw);
                e8[nt] = __ldcs(ehl_g8 + cw);
            }

            #pragma unroll
            for (int kap = 0; kap < 4; kap++) {
                uint32_t ah[4], al[4];
                #pragma unroll
                for (int i = 0; i < 2; i++) {
                    const int nt = kap * 2 + i;
                    ah[i*2+0] = eg[nt].x; al[i*2+0] = eg[nt].y;
                    ah[i*2+1] = e8[nt].x; al[i*2+1] = e8[nt].y;
                    // atten write (store-side, off the MMA critical path)
                    float2 hf = bf2f(eg[nt].x), lf = bf2f(eg[nt].y);
                    float2 h8f = bf2f(e8[nt].x), l8f = bf2f(e8[nt].y);
                    const int c = n0 + (h * 8 + nt) * 8 + t * 2;
                    __stcs((float2*)(arow_g  + c),
                           make_float2((hf.x + lf.x) * inv_g, (hf.y + lf.y) * inv_g));
                    __stcs((float2*)(arow_g8 + c),
                           make_float2((h8f.x + l8f.x) * inv_g8, (h8f.y + l8f.y) * inv_g8));
                }
                #pragma unroll
                for (int nd = 0; nd < 8; nd++) {
                    const int vbase = (nd * 8 + g) * 288 + (h * 4 + kap) * 32 + t * 8;
                    uint2 vh2 = *(const uint2*)(bufc + B_VH + vbase);
                    uint2 vl2 = *(const uint2*)(bufc + B_VL + vbase);
                    MMA(o[nd], ah, vh2.x, vh2.y);
                    MMA(o[nd], ah, vl2.x, vl2.y);
                    MMA(o[nd], al, vh2.x, vh2.y);
                }
            }
        }
        __syncthreads();   // buf[kt&1] fully read before iter kt+1 restages it
    }

    float* orow_g  = out + ((size_t)bh * SS + r0) * DD;
    float* orow_g8 = out + ((size_t)bh * SS + r8) * DD;
    #pragma unroll
    for (int nd = 0; nd < 8; nd++) {
        *(float2*)(orow_g  + nd * 8 + t * 2) = make_float2(o[nd][0] * inv_g,  o[nd][1] * inv_g);
        *(float2*)(orow_g8 + nd * 8 + t * 2) = make_float2(o[nd][2] * inv_g8, o[nd][3] * inv_g8);
    }
}

// ---------------------------------------------------------------------------
extern "C" void kernel_launch(void* const* d_in, const int* in_sizes, int n_in,
                              void* d_out, int out_size)
{
    const float* q = (const float*)d_in[0];
    const float* k = (const float*)d_in[1];
    const float* v = (const float*)d_in[2];
    const int*   mask = (const int*)d_in[3];

    float* out   = (float*)d_out;                 // [B,H,S,D]
    float* atten = out + (size_t)BH * SS * DD;    // [B,H,S,S]

    cudaFuncSetAttribute(sdpa_qk, cudaFuncAttributeMaxDynamicSharedMemorySize, SMEM_A);
    cudaFuncSetAttribute(sdpa_av, cudaFuncAttributeMaxDynamicSharedMemorySize, SMEM_B);

    mask_pack<<<1024, 256>>>(mask);
    conv_k<<<BH * SS * DD / (256 * 16), 256>>>(k);
    conv_vt<<<dim3(SS / 64, BH), 256>>>(v);
    dim3 grid(SS / 128, BH);
    sdpa_qk<<<grid, 256, SMEM_A>>>(q);
    sdpa_av<<<grid, 256, SMEM_B>>>(atten, out);
    (void)in_sizes; (void)n_in; (void)out_size;
}

// round 16
// speedup vs baseline: 1.3094x; 1.0817x over previous
#include <cuda_runtime.h>
#include <cuda_bf16.h>
#include <cuda_fp16.h>
#include <cstdint>

#define BB 2
#define HH 16
#define SS 2048
#define DD 64
#define BH (BB*HH)
#define SCALE 0.125f
#define LOG2E 1.4426950408889634f

static __device__ float g_row_s[BH * SS];
static __device__ __align__(16) uint32_t g_mbits[(size_t)BB * SS * SS / 32];  // 1MB
// K: bf16 hi/lo (packed bf16x2), PAIR-PERMUTED [0,4,1,5,2,6,3,7] per 32B group
static __device__ __align__(16) uint32_t g_kh[(size_t)BH * SS * DD / 2];
static __device__ __align__(16) uint32_t g_kl[(size_t)BH * SS * DD / 2];
// V: fp16 hi/lo (packed f16x2), transposed [bh][d][key], pair-permuted
static __device__ __align__(16) uint32_t g_vth[(size_t)BH * SS * DD / 2];
static __device__ __align__(16) uint32_t g_vtl[(size_t)BH * SS * DD / 2];
// e = exp(score) packed fp16x2: [bh][row][col/2]  (268 MB)
static __device__ __align__(16) uint32_t g_e16[(size_t)BH * SS * SS / 2];

// ---------------------------------------------------------------------------
// helpers
// ---------------------------------------------------------------------------
__device__ __forceinline__ float ex2(float x) {
    float r;
    asm("ex2.approx.f32 %0, %1;" : "=f"(r) : "f"(x));
    return r;
}
// bf16 hi/lo pack (for Q/K)
__device__ __forceinline__ void pack_hl(float a, float b, uint32_t& h, uint32_t& l) {
    asm("cvt.rn.bf16x2.f32 %0, %1, %2;" : "=r"(h) : "f"(b), "f"(a));
    float ha = __uint_as_float(h << 16);
    float hb = __uint_as_float(h & 0xffff0000u);
    asm("cvt.rn.bf16x2.f32 %0, %1, %2;" : "=r"(l) : "f"(b - hb), "f"(a - ha));
}
// fp16x2 pack (single word)
__device__ __forceinline__ uint32_t pack_f16(float a, float b) {
    uint32_t r;
    asm("cvt.rn.f16x2.f32 %0, %1, %2;" : "=r"(r) : "f"(b), "f"(a));
    return r;
}
// fp16 hi/lo pack (for V)
__device__ __forceinline__ void pack_hl16(float a, float b, uint32_t& h, uint32_t& l) {
    h = pack_f16(a, b);
    __half2 hh = *(__half2*)&h;
    float2 hf = __half22float2(hh);
    l = pack_f16(a - hf.x, b - hf.y);
}
__device__ __forceinline__ float2 h22f(uint32_t w) {
    __half2 hh = *(__half2*)&w;
    return __half22float2(hh);
}
__device__ __forceinline__ uint32_t smem_u32(const void* p) {
    uint32_t a;
    asm("{ .reg .u64 t; cvta.to.shared.u64 t, %1; cvt.u32.u64 %0, t; }"
        : "=r"(a) : "l"(p));
    return a;
}
#define CPA16(dst, src) \
    asm volatile("cp.async.cg.shared.global [%0], [%1], 16;" :: "r"(dst), "l"(src))
#define CPA_COMMIT() asm volatile("cp.async.commit_group;" ::: "memory")
#define CPA_WAIT(n)  asm volatile("cp.async.wait_group %0;" :: "n"(n) : "memory")

// bf16 MMA (QK)
#define MMA(d, a, b0v, b1v) \
    asm volatile("mma.sync.aligned.m16n8k16.row.col.f32.bf16.bf16.f32 " \
        "{%0,%1,%2,%3}, {%4,%5,%6,%7}, {%8,%9}, {%0,%1,%2,%3};" \
        : "+f"((d)[0]), "+f"((d)[1]), "+f"((d)[2]), "+f"((d)[3]) \
        : "r"((a)[0]), "r"((a)[1]), "r"((a)[2]), "r"((a)[3]), "r"(b0v), "r"(b1v))
// fp16 MMA (AV)
#define MMAH(d, a, b0v, b1v) \
    asm volatile("mma.sync.aligned.m16n8k16.row.col.f32.f16.f16.f32 " \
        "{%0,%1,%2,%3}, {%4,%5,%6,%7}, {%8,%9}, {%0,%1,%2,%3};" \
        : "+f"((d)[0]), "+f"((d)[1]), "+f"((d)[2]), "+f"((d)[3]) \
        : "r"((a)[0]), "r"((a)[1]), "r"((a)[2]), "r"((a)[3]), "r"(b0v), "r"(b1v))

// Pass A smem: double-buffered K tiles [key 128][d 64] bf16, row stride 160B.
#define A_KH 0
#define A_KL 20480
#define A_BUF 40960
#define SMEM_A (2 * A_BUF)          // 81920
// Pass B smem: double-buffered V tiles [d 64][key 128] fp16, row stride 288B.
#define B_VH 0
#define B_VL 18432
#define B_BUF 36864
#define SMEM_B (2 * B_BUF)          // 73728

// ---------------------------------------------------------------------------
// Kernel 0: bit-pack the int32 mask
// ---------------------------------------------------------------------------
__global__ __launch_bounds__(256)
void mask_pack(const int* __restrict__ mask)
{
    const size_t w = (size_t)blockIdx.x * 256 + threadIdx.x;
    const int4* p = (const int4*)mask + w * 8;
    uint32_t bits = 0;
    #pragma unroll
    for (int j = 0; j < 8; j++) {
        int4 x = p[j];
        bits |= (x.x ? 1u : 0u) << (j * 4 + 0);
        bits |= (x.y ? 1u : 0u) << (j * 4 + 1);
        bits |= (x.z ? 1u : 0u) << (j * 4 + 2);
        bits |= (x.w ? 1u : 0u) << (j * 4 + 3);
    }
    g_mbits[w] = bits;
}

// ---------------------------------------------------------------------------
// Kernel 0b: K -> bf16 hi/lo, pair-permuted within each 32B (8-pair) group.
// ---------------------------------------------------------------------------
__global__ __launch_bounds__(256)
void conv_k(const float* __restrict__ k)
{
    const size_t gi = (size_t)blockIdx.x * 256 + threadIdx.x;
    const float* kp = k + gi * 16;
    uint32_t h[8], l[8];
    #pragma unroll
    for (int i = 0; i < 4; i++) {
        float4 f = *(const float4*)(kp + i * 4);
        pack_hl(f.x, f.y, h[i*2+0], l[i*2+0]);
        pack_hl(f.z, f.w, h[i*2+1], l[i*2+1]);
    }
    *(uint4*)(g_kh + gi * 8)     = make_uint4(h[0], h[4], h[1], h[5]);
    *(uint4*)(g_kh + gi * 8 + 4) = make_uint4(h[2], h[6], h[3], h[7]);
    *(uint4*)(g_kl + gi * 8)     = make_uint4(l[0], l[4], l[1], l[5]);
    *(uint4*)(g_kl + gi * 8 + 4) = make_uint4(l[2], l[6], l[3], l[7]);
}

// ---------------------------------------------------------------------------
// Kernel 0c: V -> fp16 hi/lo transposed [bh][d][key], pair-permuted per group.
// ---------------------------------------------------------------------------
__global__ __launch_bounds__(256)
void conv_vt(const float* __restrict__ v)
{
    __shared__ float ts[64][65];
    const int tid = threadIdx.x;
    const int bh  = blockIdx.y;
    const int n0  = blockIdx.x * 64;

    const int r  = tid >> 2;
    const int c0 = (tid & 3) * 16;
    const float* vp = v + ((size_t)bh * SS + n0 + r) * DD + c0;
    #pragma unroll
    for (int i = 0; i < 4; i++) {
        float4 f = *(const float4*)(vp + i * 4);
        ts[r][c0 + i*4 + 0] = f.x;
        ts[r][c0 + i*4 + 1] = f.y;
        ts[r][c0 + i*4 + 2] = f.z;
        ts[r][c0 + i*4 + 3] = f.w;
    }
    __syncthreads();

    const int d  = tid >> 2;
    const int kc = (tid & 3) * 16;
    uint32_t h[8], l[8];
    #pragma unroll
    for (int m = 0; m < 8; m++)
        pack_hl16(ts[kc + 2*m][d], ts[kc + 2*m + 1][d], h[m], l[m]);
    const size_t o = (((size_t)bh * DD + d) * SS + n0 + kc) / 2;
    *(uint4*)(g_vth + o)     = make_uint4(h[0], h[4], h[1], h[5]);
    *(uint4*)(g_vth + o + 4) = make_uint4(h[2], h[6], h[3], h[7]);
    *(uint4*)(g_vtl + o)     = make_uint4(l[0], l[4], l[1], l[5]);
    *(uint4*)(g_vtl + o + 4) = make_uint4(l[2], l[6], l[3], l[7]);
}

// ---------------------------------------------------------------------------
// Q fragments (bf16 hi/lo), scale*log2e folded in
// ---------------------------------------------------------------------------
__device__ __forceinline__ void load_q_frags(const float* __restrict__ q,
                                             int bh, int r0, int r8, int t,
                                             uint32_t (&qh)[4][4], uint32_t (&ql)[4][4])
{
    const float* qp = q + (size_t)bh * SS * DD;
    const float sc = SCALE * LOG2E;
    #pragma unroll
    for (int ks = 0; ks < 4; ks++) {
        const int c = ks * 16 + t * 2;
        float2 x0 = *(const float2*)(qp + (size_t)r0 * DD + c);
        float2 x1 = *(const float2*)(qp + (size_t)r8 * DD + c);
        float2 x2 = *(const float2*)(qp + (size_t)r0 * DD + c + 8);
        float2 x3 = *(const float2*)(qp + (size_t)r8 * DD + c + 8);
        pack_hl(x0.x * sc, x0.y * sc, qh[ks][0], ql[ks][0]);
        pack_hl(x1.x * sc, x1.y * sc, qh[ks][1], ql[ks][1]);
        pack_hl(x2.x * sc, x2.y * sc, qh[ks][2], ql[ks][2]);
        pack_hl(x3.x * sc, x3.y * sc, qh[ks][3], ql[ks][3]);
    }
}

// ---------------------------------------------------------------------------
// Pass A: QK (bf16x3) -> e = exp(masked score) -> g_e16 (fp16x2), rowsums.
// K tiles double-buffered via cp.async. (R13 structure.)
// ---------------------------------------------------------------------------
__device__ __forceinline__ void stage_k(uint32_t sbuf, const char* kh_b,
                                        const char* kl_b, int n0, int tid)
{
    #pragma unroll
    for (int cc = 0; cc < 4; cc++) {
        const int c  = tid + cc * 256;          // 0..1023
        const int kr = c >> 3, kc = c & 7;
        const size_t src = (size_t)(n0 + kr) * (DD * 2) + kc * 16;
        const uint32_t dst = kr * 160 + kc * 16;
        CPA16(sbuf + A_KH + dst, kh_b + src);
        CPA16(sbuf + A_KL + dst, kl_b + src);
    }
}

__global__ void __launch_bounds__(256, 2)
sdpa_qk(const float* __restrict__ q)
{
    extern __shared__ char smem[];
    const int tid  = threadIdx.x;
    const int lane = tid & 31;
    const int g    = lane >> 2;
    const int t    = lane & 3;
    const int w    = tid >> 5;
    const int bh   = blockIdx.y;
    const int b    = bh / HH;
    const int q0   = blockIdx.x * 128;
    const int r0   = q0 + w * 16 + g;
    const int r8   = r0 + 8;
    const uint32_t sb = smem_u32(smem);

    const size_t mb0 = ((size_t)b * SS + r0) * 64;
    const size_t mb8 = ((size_t)b * SS + r8) * 64;
    uint32_t* e_g  = g_e16 + ((size_t)bh * SS + r0) * (SS / 2);
    uint32_t* e_g8 = g_e16 + ((size_t)bh * SS + r8) * (SS / 2);

    const char* kh_b = (const char*)g_kh + (size_t)bh * SS * DD * 2;
    const char* kl_b = (const char*)g_kl + (size_t)bh * SS * DD * 2;

    stage_k(sb, kh_b, kl_b, 0, tid);
    CPA_COMMIT();

    uint32_t qh[4][4], ql[4][4];
    load_q_frags(q, bh, r0, r8, t, qh, ql);

    float sum_g = 0.0f, sum_g8 = 0.0f;

    #pragma unroll 1
    for (int kt = 0; kt < 16; kt++) {
        const int n0 = kt * 128;
        const char* bufc = smem + (kt & 1) * A_BUF;

        if (kt + 1 < 16) {
            stage_k(sb + ((kt + 1) & 1) * A_BUF, kh_b, kl_b, (kt + 1) * 128, tid);
            CPA_COMMIT();
            CPA_WAIT(1);
        } else {
            CPA_WAIT(0);
        }
        __syncthreads();

        uint4 mg = *(const uint4*)(g_mbits + mb0 + n0 / 32);
        uint4 m8 = *(const uint4*)(g_mbits + mb8 + n0 / 32);
        const uint32_t* mgw = (const uint32_t*)&mg;
        const uint32_t* m8w = (const uint32_t*)&m8;

        #pragma unroll
        for (int h = 0; h < 2; h++) {
            float s[8][4];
            #pragma unroll
            for (int nt = 0; nt < 8; nt++)
                #pragma unroll
                for (int i = 0; i < 4; i++) s[nt][i] = 0.0f;

            #pragma unroll
            for (int ks = 0; ks < 4; ks++) {
                #pragma unroll
                for (int pass = 0; pass < 3; pass++) {
                    const uint32_t* A = (pass == 2) ? ql[ks] : qh[ks];
                    const int bb = (pass == 1) ? A_KL : A_KH;
                    #pragma unroll
                    for (int nt = 0; nt < 8; nt++) {
                        const char* ad = bufc + bb + ((h * 8 + nt) * 8 + g) * 160
                                       + ks * 32 + t * 8;
                        uint2 b01 = *(const uint2*)ad;   // LDS.64 pairs (p, p+4)
                        MMA(s[nt], A, b01.x, b01.y);
                    }
                }
            }

            #pragma unroll
            for (int nt = 0; nt < 8; nt++) {
                const int ntg = h * 8 + nt;
                const uint32_t wg = mgw[ntg >> 2] >> ((ntg & 3) * 8 + t * 2);
                const uint32_t w8 = m8w[ntg >> 2] >> ((ntg & 3) * 8 + t * 2);
                const float e0 = (wg      & 1) ? 0.0f : ex2(s[nt][0]);
                const float e1 = (wg >> 1 & 1) ? 0.0f : ex2(s[nt][1]);
                const float e2 = (w8      & 1) ? 0.0f : ex2(s[nt][2]);
                const float e3 = (w8 >> 1 & 1) ? 0.0f : ex2(s[nt][3]);
                sum_g  += e0 + e1;
                sum_g8 += e2 + e3;
                const int cw = (n0 + ntg * 8) / 2 + t;   // word index in row
                __stcs(e_g  + cw, pack_f16(e0, e1));
                __stcs(e_g8 + cw, pack_f16(e2, e3));
            }
        }
        __syncthreads();
    }

    sum_g  += __shfl_xor_sync(0xffffffffu, sum_g, 1);
    sum_g  += __shfl_xor_sync(0xffffffffu, sum_g, 2);
    sum_g8 += __shfl_xor_sync(0xffffffffu, sum_g8, 1);
    sum_g8 += __shfl_xor_sync(0xffffffffu, sum_g8, 2);
    if (t == 0) {
        g_row_s[bh * SS + r0] = sum_g;
        g_row_s[bh * SS + r8] = sum_g8;
    }
}

// ---------------------------------------------------------------------------
// Pass B: fp16 A-frags from g_e16; atten = e*inv (fp32 write); out = (sum e*V)*inv.
// AV = fp16 MMA x2 (V hi/lo). V tiles double-buffered. (R13 structure.)
// ---------------------------------------------------------------------------
__device__ __forceinline__ void stage_v(uint32_t sbuf, const char* vh_b,
                                        const char* vl_b, int n0, int tid)
{
    #pragma unroll
    for (int cc = 0; cc < 4; cc++) {
        const int c  = tid + cc * 256;          // 0..1023
        const int vd = c >> 4, vc = c & 15;
        const size_t src = ((size_t)vd * SS + n0) * 2 + vc * 16;
        const uint32_t dst = vd * 288 + vc * 16;
        CPA16(sbuf + B_VH + dst, vh_b + src);
        CPA16(sbuf + B_VL + dst, vl_b + src);
    }
}

__global__ void __launch_bounds__(256, 2)
sdpa_av(float* __restrict__ atten, float* __restrict__ out)
{
    extern __shared__ char smem[];
    const int tid  = threadIdx.x;
    const int lane = tid & 31;
    const int g    = lane >> 2;
    const int t    = lane & 3;
    const int w    = tid >> 5;
    const int bh   = blockIdx.y;
    const int q0   = blockIdx.x * 128;
    const int r0   = q0 + w * 16 + g;
    const int r8   = r0 + 8;
    const uint32_t sb = smem_u32(smem);

    float* arow_g  = atten + ((size_t)bh * SS + r0) * SS;
    float* arow_g8 = atten + ((size_t)bh * SS + r8) * SS;
    const uint32_t* e_g  = g_e16 + ((size_t)bh * SS + r0) * (SS / 2);
    const uint32_t* e_g8 = g_e16 + ((size_t)bh * SS + r8) * (SS / 2);

    const char* vh_b = (const char*)g_vth + (size_t)bh * SS * DD * 2;
    const char* vl_b = (const char*)g_vtl + (size_t)bh * SS * DD * 2;

    stage_v(sb, vh_b, vl_b, 0, tid);
    CPA_COMMIT();

    const float inv_g  = 1.0f / g_row_s[bh * SS + r0];
    const float inv_g8 = 1.0f / g_row_s[bh * SS + r8];

    float o[8][4];
    #pragma unroll
    for (int nd = 0; nd < 8; nd++)
        #pragma unroll
        for (int i = 0; i < 4; i++) o[nd][i] = 0.0f;

    #pragma unroll 1
    for (int kt = 0; kt < 16; kt++) {
        const int n0 = kt * 128;
        const char* bufc = smem + (kt & 1) * B_BUF;

        if (kt + 1 < 16) {
            stage_v(sb + ((kt + 1) & 1) * B_BUF, vh_b, vl_b, (kt + 1) * 128, tid);
            CPA_COMMIT();
            CPA_WAIT(1);
        } else {
            CPA_WAIT(0);
        }
        __syncthreads();

        #pragma unroll
        for (int h = 0; h < 2; h++) {
            // load this half's fp16x2 fragment words (independent loads)
            uint32_t eg[8], e8[8];
            #pragma unroll
            for (int nt = 0; nt < 8; nt++) {
                const int cw = (n0 + (h * 8 + nt) * 8) / 2 + t;
                eg[nt] = __ldcs(e_g  + cw);
                e8[nt] = __ldcs(e_g8 + cw);
            }

            #pragma unroll
            for (int kap = 0; kap < 4; kap++) {
                uint32_t ah[4];
                #pragma unroll
                for (int i = 0; i < 2; i++) {
                    const int nt = kap * 2 + i;
                    ah[i*2+0] = eg[nt];
                    ah[i*2+1] = e8[nt];
                    // atten write (store-side, off the MMA critical path)
                    float2 pg = h22f(eg[nt]);
                    float2 p8 = h22f(e8[nt]);
                    const int c = n0 + (h * 8 + nt) * 8 + t * 2;
                    __stcs((float2*)(arow_g  + c),
                           make_float2(pg.x * inv_g, pg.y * inv_g));
                    __stcs((float2*)(arow_g8 + c),
                           make_float2(p8.x * inv_g8, p8.y * inv_g8));
                }
                #pragma unroll
                for (int nd = 0; nd < 8; nd++) {
                    const int vbase = (nd * 8 + g) * 288 + (h * 4 + kap) * 32 + t * 8;
                    uint2 vh2 = *(const uint2*)(bufc + B_VH + vbase);
                    uint2 vl2 = *(const uint2*)(bufc + B_VL + vbase);
                    MMAH(o[nd], ah, vh2.x, vh2.y);
                    MMAH(o[nd], ah, vl2.x, vl2.y);
                }
            }
        }
        __syncthreads();
    }

    float* orow_g  = out + ((size_t)bh * SS + r0) * DD;
    float* orow_g8 = out + ((size_t)bh * SS + r8) * DD;
    #pragma unroll
    for (int nd = 0; nd < 8; nd++) {
        *(float2*)(orow_g  + nd * 8 + t * 2) = make_float2(o[nd][0] * inv_g,  o[nd][1] * inv_g);
        *(float2*)(orow_g8 + nd * 8 + t * 2) = make_float2(o[nd][2] * inv_g8, o[nd][3] * inv_g8);
    }
}

// ---------------------------------------------------------------------------
extern "C" void kernel_launch(void* const* d_in, const int* in_sizes, int n_in,
                              void* d_out, int out_size)
{
    const float* q = (const float*)d_in[0];
    const float* k = (const float*)d_in[1];
    const float* v = (const float*)d_in[2];
    const int*   mask = (const int*)d_in[3];

    float* out   = (float*)d_out;                 // [B,H,S,D]
    float* atten = out + (size_t)BH * SS * DD;    // [B,H,S,S]

    cudaFuncSetAttribute(sdpa_qk, cudaFuncAttributeMaxDynamicSharedMemorySize, SMEM_A);
    cudaFuncSetAttribute(sdpa_av, cudaFuncAttributeMaxDynamicSharedMemorySize, SMEM_B);

    mask_pack<<<1024, 256>>>(mask);
    conv_k<<<BH * SS * DD / (256 * 16), 256>>>(k);
    conv_vt<<<dim3(SS / 64, BH), 256>>>(v);
    dim3 grid(SS / 128, BH);
    sdpa_qk<<<grid, 256, SMEM_A>>>(q);
    sdpa_av<<<grid, 256, SMEM_B>>>(atten, out);
    (void)in_sizes; (void)n_in; (void)out_size;
}

// round 17
// speedup vs baseline: 1.4640x; 1.1181x over previous
#include <cuda_runtime.h>
#include <cuda_bf16.h>
#include <cuda_fp16.h>
#include <cstdint>

#define BB 2
#define HH 16
#define SS 2048
#define DD 64
#define BH (BB*HH)
#define SCALE 0.125f
#define LOG2E 1.4426950408889634f

static __device__ float g_row_s[BH * SS];
static __device__ __align__(16) uint32_t g_mbits[(size_t)BB * SS * SS / 32];  // 1MB
// K: single fp16 (packed f16x2), PAIR-PERMUTED [0,4,1,5,2,6,3,7] per 32B group
static __device__ __align__(16) uint32_t g_k16[(size_t)BH * SS * DD / 2];
// V: fp16 hi/lo (packed f16x2), transposed [bh][d][key], pair-permuted
static __device__ __align__(16) uint32_t g_vth[(size_t)BH * SS * DD / 2];
static __device__ __align__(16) uint32_t g_vtl[(size_t)BH * SS * DD / 2];
// e = exp(score) packed fp16x2: [bh][row][col/2]  (268 MB)
static __device__ __align__(16) uint32_t g_e16[(size_t)BH * SS * SS / 2];

// ---------------------------------------------------------------------------
// helpers
// ---------------------------------------------------------------------------
__device__ __forceinline__ float ex2(float x) {
    float r;
    asm("ex2.approx.f32 %0, %1;" : "=f"(r) : "f"(x));
    return r;
}
// fp16x2 pack (single word)
__device__ __forceinline__ uint32_t pack_f16(float a, float b) {
    uint32_t r;
    asm("cvt.rn.f16x2.f32 %0, %1, %2;" : "=r"(r) : "f"(b), "f"(a));
    return r;
}
// fp16 hi/lo pack
__device__ __forceinline__ void pack_hl16(float a, float b, uint32_t& h, uint32_t& l) {
    h = pack_f16(a, b);
    __half2 hh = *(__half2*)&h;
    float2 hf = __half22float2(hh);
    l = pack_f16(a - hf.x, b - hf.y);
}
__device__ __forceinline__ float2 h22f(uint32_t w) {
    __half2 hh = *(__half2*)&w;
    return __half22float2(hh);
}
__device__ __forceinline__ uint32_t smem_u32(const void* p) {
    uint32_t a;
    asm("{ .reg .u64 t; cvta.to.shared.u64 t, %1; cvt.u32.u64 %0, t; }"
        : "=r"(a) : "l"(p));
    return a;
}
#define CPA16(dst, src) \
    asm volatile("cp.async.cg.shared.global [%0], [%1], 16;" :: "r"(dst), "l"(src))
#define CPA_COMMIT() asm volatile("cp.async.commit_group;" ::: "memory")
#define CPA_WAIT(n)  asm volatile("cp.async.wait_group %0;" :: "n"(n) : "memory")

// fp16 MMA
#define MMAH(d, a, b0v, b1v) \
    asm volatile("mma.sync.aligned.m16n8k16.row.col.f32.f16.f16.f32 " \
        "{%0,%1,%2,%3}, {%4,%5,%6,%7}, {%8,%9}, {%0,%1,%2,%3};" \
        : "+f"((d)[0]), "+f"((d)[1]), "+f"((d)[2]), "+f"((d)[3]) \
        : "r"((a)[0]), "r"((a)[1]), "r"((a)[2]), "r"((a)[3]), "r"(b0v), "r"(b1v))

// Pass A smem: double-buffered single-fp16 K tiles [key 128][d 64], row stride 160B.
#define A_BUF 20480
#define SMEM_A (2 * A_BUF)          // 40960
// Pass B smem: double-buffered V tiles [d 64][key 128] fp16 hi/lo, row stride 288B.
#define B_VH 0
#define B_VL 18432
#define B_BUF 36864
#define SMEM_B (2 * B_BUF)          // 73728

// ---------------------------------------------------------------------------
// Kernel 0: bit-pack the int32 mask
// ---------------------------------------------------------------------------
__global__ __launch_bounds__(256)
void mask_pack(const int* __restrict__ mask)
{
    const size_t w = (size_t)blockIdx.x * 256 + threadIdx.x;
    const int4* p = (const int4*)mask + w * 8;
    uint32_t bits = 0;
    #pragma unroll
    for (int j = 0; j < 8; j++) {
        int4 x = p[j];
        bits |= (x.x ? 1u : 0u) << (j * 4 + 0);
        bits |= (x.y ? 1u : 0u) << (j * 4 + 1);
        bits |= (x.z ? 1u : 0u) << (j * 4 + 2);
        bits |= (x.w ? 1u : 0u) << (j * 4 + 3);
    }
    g_mbits[w] = bits;
}

// ---------------------------------------------------------------------------
// Kernel 0b: K -> single fp16, pair-permuted within each 32B (8-pair) group.
// ---------------------------------------------------------------------------
__global__ __launch_bounds__(256)
void conv_k(const float* __restrict__ k)
{
    const size_t gi = (size_t)blockIdx.x * 256 + threadIdx.x;
    const float* kp = k + gi * 16;
    uint32_t h[8];
    #pragma unroll
    for (int i = 0; i < 4; i++) {
        float4 f = *(const float4*)(kp + i * 4);
        h[i*2+0] = pack_f16(f.x, f.y);
        h[i*2+1] = pack_f16(f.z, f.w);
    }
    *(uint4*)(g_k16 + gi * 8)     = make_uint4(h[0], h[4], h[1], h[5]);
    *(uint4*)(g_k16 + gi * 8 + 4) = make_uint4(h[2], h[6], h[3], h[7]);
}

// ---------------------------------------------------------------------------
// Kernel 0c: V -> fp16 hi/lo transposed [bh][d][key], pair-permuted per group.
// ---------------------------------------------------------------------------
__global__ __launch_bounds__(256)
void conv_vt(const float* __restrict__ v)
{
    __shared__ float ts[64][65];
    const int tid = threadIdx.x;
    const int bh  = blockIdx.y;
    const int n0  = blockIdx.x * 64;

    const int r  = tid >> 2;
    const int c0 = (tid & 3) * 16;
    const float* vp = v + ((size_t)bh * SS + n0 + r) * DD + c0;
    #pragma unroll
    for (int i = 0; i < 4; i++) {
        float4 f = *(const float4*)(vp + i * 4);
        ts[r][c0 + i*4 + 0] = f.x;
        ts[r][c0 + i*4 + 1] = f.y;
        ts[r][c0 + i*4 + 2] = f.z;
        ts[r][c0 + i*4 + 3] = f.w;
    }
    __syncthreads();

    const int d  = tid >> 2;
    const int kc = (tid & 3) * 16;
    uint32_t h[8], l[8];
    #pragma unroll
    for (int m = 0; m < 8; m++)
        pack_hl16(ts[kc + 2*m][d], ts[kc + 2*m + 1][d], h[m], l[m]);
    const size_t o = (((size_t)bh * DD + d) * SS + n0 + kc) / 2;
    *(uint4*)(g_vth + o)     = make_uint4(h[0], h[4], h[1], h[5]);
    *(uint4*)(g_vth + o + 4) = make_uint4(h[2], h[6], h[3], h[7]);
    *(uint4*)(g_vtl + o)     = make_uint4(l[0], l[4], l[1], l[5]);
    *(uint4*)(g_vtl + o + 4) = make_uint4(l[2], l[6], l[3], l[7]);
}

// ---------------------------------------------------------------------------
// Q fragments (fp16 hi/lo), scale*log2e folded in
// ---------------------------------------------------------------------------
__device__ __forceinline__ void load_q_frags(const float* __restrict__ q,
                                             int bh, int r0, int r8, int t,
                                             uint32_t (&qh)[4][4], uint32_t (&ql)[4][4])
{
    const float* qp = q + (size_t)bh * SS * DD;
    const float sc = SCALE * LOG2E;
    #pragma unroll
    for (int ks = 0; ks < 4; ks++) {
        const int c = ks * 16 + t * 2;
        float2 x0 = *(const float2*)(qp + (size_t)r0 * DD + c);
        float2 x1 = *(const float2*)(qp + (size_t)r8 * DD + c);
        float2 x2 = *(const float2*)(qp + (size_t)r0 * DD + c + 8);
        float2 x3 = *(const float2*)(qp + (size_t)r8 * DD + c + 8);
        pack_hl16(x0.x * sc, x0.y * sc, qh[ks][0], ql[ks][0]);
        pack_hl16(x1.x * sc, x1.y * sc, qh[ks][1], ql[ks][1]);
        pack_hl16(x2.x * sc, x2.y * sc, qh[ks][2], ql[ks][2]);
        pack_hl16(x3.x * sc, x3.y * sc, qh[ks][3], ql[ks][3]);
    }
}

// ---------------------------------------------------------------------------
// Pass A: QK (fp16x2: qh*k + ql*k) -> e = exp(masked score) -> g_e16, rowsums.
// Single-fp16 K tiles double-buffered via cp.async.
// ---------------------------------------------------------------------------
__device__ __forceinline__ void stage_k(uint32_t sbuf, const char* k_b,
                                        int n0, int tid)
{
    #pragma unroll
    for (int cc = 0; cc < 4; cc++) {
        const int c  = tid + cc * 256;          // 0..1023
        const int kr = c >> 3, kc = c & 7;
        const size_t src = (size_t)(n0 + kr) * (DD * 2) + kc * 16;
        CPA16(sbuf + kr * 160 + kc * 16, k_b + src);
    }
}

__global__ void __launch_bounds__(256, 2)
sdpa_qk(const float* __restrict__ q)
{
    extern __shared__ char smem[];
    const int tid  = threadIdx.x;
    const int lane = tid & 31;
    const int g    = lane >> 2;
    const int t    = lane & 3;
    const int w    = tid >> 5;
    const int bh   = blockIdx.y;
    const int b    = bh / HH;
    const int q0   = blockIdx.x * 128;
    const int r0   = q0 + w * 16 + g;
    const int r8   = r0 + 8;
    const uint32_t sb = smem_u32(smem);

    const size_t mb0 = ((size_t)b * SS + r0) * 64;
    const size_t mb8 = ((size_t)b * SS + r8) * 64;
    uint32_t* e_g  = g_e16 + ((size_t)bh * SS + r0) * (SS / 2);
    uint32_t* e_g8 = g_e16 + ((size_t)bh * SS + r8) * (SS / 2);

    const char* k_b = (const char*)g_k16 + (size_t)bh * SS * DD * 2;

    stage_k(sb, k_b, 0, tid);
    CPA_COMMIT();

    uint32_t qh[4][4], ql[4][4];
    load_q_frags(q, bh, r0, r8, t, qh, ql);

    float sum_g = 0.0f, sum_g8 = 0.0f;

    #pragma unroll 1
    for (int kt = 0; kt < 16; kt++) {
        const int n0 = kt * 128;
        const char* bufc = smem + (kt & 1) * A_BUF;

        if (kt + 1 < 16) {
            stage_k(sb + ((kt + 1) & 1) * A_BUF, k_b, (kt + 1) * 128, tid);
            CPA_COMMIT();
            CPA_WAIT(1);
        } else {
            CPA_WAIT(0);
        }
        __syncthreads();

        uint4 mg = *(const uint4*)(g_mbits + mb0 + n0 / 32);
        uint4 m8 = *(const uint4*)(g_mbits + mb8 + n0 / 32);
        const uint32_t* mgw = (const uint32_t*)&mg;
        const uint32_t* m8w = (const uint32_t*)&m8;

        #pragma unroll
        for (int h = 0; h < 2; h++) {
            float s[8][4];
            #pragma unroll
            for (int nt = 0; nt < 8; nt++)
                #pragma unroll
                for (int i = 0; i < 4; i++) s[nt][i] = 0.0f;

            #pragma unroll
            for (int ks = 0; ks < 4; ks++) {
                #pragma unroll
                for (int nt = 0; nt < 8; nt++) {
                    const char* ad = bufc + ((h * 8 + nt) * 8 + g) * 160
                                   + ks * 32 + t * 8;
                    uint2 b01 = *(const uint2*)ad;   // LDS.64, shared by both passes
                    MMAH(s[nt], qh[ks], b01.x, b01.y);
                    MMAH(s[nt], ql[ks], b01.x, b01.y);
                }
            }

            #pragma unroll
            for (int nt = 0; nt < 8; nt++) {
                const int ntg = h * 8 + nt;
                const uint32_t wg = mgw[ntg >> 2] >> ((ntg & 3) * 8 + t * 2);
                const uint32_t w8 = m8w[ntg >> 2] >> ((ntg & 3) * 8 + t * 2);
                const float e0 = (wg      & 1) ? 0.0f : ex2(s[nt][0]);
                const float e1 = (wg >> 1 & 1) ? 0.0f : ex2(s[nt][1]);
                const float e2 = (w8      & 1) ? 0.0f : ex2(s[nt][2]);
                const float e3 = (w8 >> 1 & 1) ? 0.0f : ex2(s[nt][3]);
                sum_g  += e0 + e1;
                sum_g8 += e2 + e3;
                const int cw = (n0 + ntg * 8) / 2 + t;   // word index in row
                __stcs(e_g  + cw, pack_f16(e0, e1));
                __stcs(e_g8 + cw, pack_f16(e2, e3));
            }
        }
        __syncthreads();
    }

    sum_g  += __shfl_xor_sync(0xffffffffu, sum_g, 1);
    sum_g  += __shfl_xor_sync(0xffffffffu, sum_g, 2);
    sum_g8 += __shfl_xor_sync(0xffffffffu, sum_g8, 1);
    sum_g8 += __shfl_xor_sync(0xffffffffu, sum_g8, 2);
    if (t == 0) {
        g_row_s[bh * SS + r0] = sum_g;
        g_row_s[bh * SS + r8] = sum_g8;
    }
}

// ---------------------------------------------------------------------------
// Pass B: fp16 A-frags from g_e16; atten = e*inv; out = (sum e*V)*inv.
// AV = fp16 MMA x2 (V hi/lo). V tiles double-buffered. (R16, unchanged.)
// ---------------------------------------------------------------------------
__device__ __forceinline__ void stage_v(uint32_t sbuf, const char* vh_b,
                                        const char* vl_b, int n0, int tid)
{
    #pragma unroll
    for (int cc = 0; cc < 4; cc++) {
        const int c  = tid + cc * 256;          // 0..1023
        const int vd = c >> 4, vc = c & 15;
        const size_t src = ((size_t)vd * SS + n0) * 2 + vc * 16;
        const uint32_t dst = vd * 288 + vc * 16;
        CPA16(sbuf + B_VH + dst, vh_b + src);
        CPA16(sbuf + B_VL + dst, vl_b + src);
    }
}

__global__ void __launch_bounds__(256, 2)
sdpa_av(float* __restrict__ atten, float* __restrict__ out)
{
    extern __shared__ char smem[];
    const int tid  = threadIdx.x;
    const int lane = tid & 31;
    const int g    = lane >> 2;
    const int t    = lane & 3;
    const int w    = tid >> 5;
    const int bh   = blockIdx.y;
    const int q0   = blockIdx.x * 128;
    const int r0   = q0 + w * 16 + g;
    const int r8   = r0 + 8;
    const uint32_t sb = smem_u32(smem);

    float* arow_g  = atten + ((size_t)bh * SS + r0) * SS;
    float* arow_g8 = atten + ((size_t)bh * SS + r8) * SS;
    const uint32_t* e_g  = g_e16 + ((size_t)bh * SS + r0) * (SS / 2);
    const uint32_t* e_g8 = g_e16 + ((size_t)bh * SS + r8) * (SS / 2);

    const char* vh_b = (const char*)g_vth + (size_t)bh * SS * DD * 2;
    const char* vl_b = (const char*)g_vtl + (size_t)bh * SS * DD * 2;

    stage_v(sb, vh_b, vl_b, 0, tid);
    CPA_COMMIT();

    const float inv_g  = 1.0f / g_row_s[bh * SS + r0];
    const float inv_g8 = 1.0f / g_row_s[bh * SS + r8];

    float o[8][4];
    #pragma unroll
    for (int nd = 0; nd < 8; nd++)
        #pragma unroll
        for (int i = 0; i < 4; i++) o[nd][i] = 0.0f;

    #pragma unroll 1
    for (int kt = 0; kt < 16; kt++) {
        const int n0 = kt * 128;
        const char* bufc = smem + (kt & 1) * B_BUF;

        if (kt + 1 < 16) {
            stage_v(sb + ((kt + 1) & 1) * B_BUF, vh_b, vl_b, (kt + 1) * 128, tid);
            CPA_COMMIT();
            CPA_WAIT(1);
        } else {
            CPA_WAIT(0);
        }
        __syncthreads();

        #pragma unroll
        for (int h = 0; h < 2; h++) {
            uint32_t eg[8], e8[8];
            #pragma unroll
            for (int nt = 0; nt < 8; nt++) {
                const int cw = (n0 + (h * 8 + nt) * 8) / 2 + t;
                eg[nt] = __ldcs(e_g  + cw);
                e8[nt] = __ldcs(e_g8 + cw);
            }

            #pragma unroll
            for (int kap = 0; kap < 4; kap++) {
                uint32_t ah[4];
                #pragma unroll
                for (int i = 0; i < 2; i++) {
                    const int nt = kap * 2 + i;
                    ah[i*2+0] = eg[nt];
                    ah[i*2+1] = e8[nt];
                    float2 pg = h22f(eg[nt]);
                    float2 p8 = h22f(e8[nt]);
                    const int c = n0 + (h * 8 + nt) * 8 + t * 2;
                    __stcs((float2*)(arow_g  + c),
                           make_float2(pg.x * inv_g, pg.y * inv_g));
                    __stcs((float2*)(arow_g8 + c),
                           make_float2(p8.x * inv_g8, p8.y * inv_g8));
                }
                #pragma unroll
                for (int nd = 0; nd < 8; nd++) {
                    const int vbase = (nd * 8 + g) * 288 + (h * 4 + kap) * 32 + t * 8;
                    uint2 vh2 = *(const uint2*)(bufc + B_VH + vbase);
                    uint2 vl2 = *(const uint2*)(bufc + B_VL + vbase);
                    MMAH(o[nd], ah, vh2.x, vh2.y);
                    MMAH(o[nd], ah, vl2.x, vl2.y);
                }
            }
        }
        __syncthreads();
    }

    float* orow_g  = out + ((size_t)bh * SS + r0) * DD;
    float* orow_g8 = out + ((size_t)bh * SS + r8) * DD;
    #pragma unroll
    for (int nd = 0; nd < 8; nd++) {
        *(float2*)(orow_g  + nd * 8 + t * 2) = make_float2(o[nd][0] * inv_g,  o[nd][1] * inv_g);
        *(float2*)(orow_g8 + nd * 8 + t * 2) = make_float2(o[nd][2] * inv_g8, o[nd][3] * inv_g8);
    }
}

// ---------------------------------------------------------------------------
extern "C" void kernel_launch(void* const* d_in, const int* in_sizes, int n_in,
                              void* d_out, int out_size)
{
    const float* q = (const float*)d_in[0];
    const float* k = (const float*)d_in[1];
    const float* v = (const float*)d_in[2];
    const int*   mask = (const int*)d_in[3];

    float* out   = (float*)d_out;                 // [B,H,S,D]
    float* atten = out + (size_t)BH * SS * DD;    // [B,H,S,S]

    cudaFuncSetAttribute(sdpa_qk, cudaFuncAttributeMaxDynamicSharedMemorySize, SMEM_A);
    cudaFuncSetAttribute(sdpa_av, cudaFuncAttributeMaxDynamicSharedMemorySize, SMEM_B);

    mask_pack<<<1024, 256>>>(mask);
    conv_k<<<BH * SS * DD / (256 * 16), 256>>>(k);
    conv_vt<<<dim3(SS / 64, BH), 256>>>(v);
    dim3 grid(SS / 128, BH);
    sdpa_qk<<<grid, 256, SMEM_A>>>(q);
    sdpa_av<<<grid, 256, SMEM_B>>>(atten, out);
    (void)in_sizes; (void)n_in; (void)out_size;
}